// round 1
// baseline (speedup 1.0000x reference)
#include <cuda_runtime.h>
#include <math.h>

#define N_DRUG 20000
#define N_DIS  20000
#define NEDGE  300000
#define DIM    128

// ---------------- scratch (device globals; no allocation allowed) ----------
__device__ float g_Wh_ind[N_DRUG * DIM];
__device__ float g_Wh_rev[N_DIS * DIM];
__device__ float g_Wh_dd [N_DIS * DIM];

__device__ float g_el_ind[N_DRUG];  // Wh_ind . a_ind[:D]   (src key, etype ind)
__device__ float g_er_rev[N_DRUG];  // Wh_ind . a_rev[D:]   (dst key, etype rev)
__device__ float g_el_rev[N_DIS];   // Wh_rev . a_rev[:D]   (src key, etype rev)
__device__ float g_er_ind[N_DIS];   // Wh_rev . a_ind[D:]   (dst key, etype ind)
__device__ float g_el_dd [N_DIS];   // Wh_dd  . a_dd[:D]
__device__ float g_er_dd [N_DIS];   // Wh_dd  . a_dd[D:]

__device__ float g_m[3][N_DIS];     // per-etype segment max   (N_DRUG == N_DIS)
__device__ float g_s[3][N_DIS];     // per-etype softmax denom

// ---------------- helpers ---------------------------------------------------
__device__ __forceinline__ void atomicMaxFloat(float* addr, float val) {
    if (val >= 0.0f) {
        atomicMax((int*)addr, __float_as_int(val));
    } else {
        atomicMin((unsigned int*)addr, __float_as_uint(val));
    }
}

__device__ __forceinline__ float leaky(float x) {
    return x > 0.0f ? x : 0.01f * x;
}

// ---------------- init: zero output, init m/s ------------------------------
__global__ void init_kernel(float* __restrict__ out, int out_n) {
    int i = blockIdx.x * blockDim.x + threadIdx.x;
    if (i < out_n) {
        out[i] = 0.0f;
    } else {
        int k = i - out_n;
        if (k < 3 * N_DIS) {
            (&g_m[0][0])[k] = -INFINITY;
        } else {
            k -= 3 * N_DIS;
            if (k < 3 * N_DIS) (&g_s[0][0])[k] = 0.0f;
        }
    }
}

// ---------------- fused GEMM + bias + attention scalar projections ---------
// Wh[row] = X[row] @ W + b ;  s1[row] = Wh[row].a1 ; s2[row] = Wh[row].a2
// 128 threads/block, 4 rows/block (W element reused 4x per load).
__global__ void __launch_bounds__(128) gemm_proj_kernel(
    const float* __restrict__ X, const float* __restrict__ W,
    const float* __restrict__ b, const float* __restrict__ a1,
    const float* __restrict__ a2,
    float* __restrict__ Wh, float* __restrict__ s1, float* __restrict__ s2,
    int n)
{
    const int R = 4;
    __shared__ float xs[R][DIM];
    __shared__ float red[2 * R][4];

    int j    = threadIdx.x;          // output column 0..127
    int row0 = blockIdx.x * R;

    #pragma unroll
    for (int r = 0; r < R; r++) {
        int row = row0 + r;
        xs[r][j] = (row < n) ? X[row * DIM + j] : 0.0f;
    }
    __syncthreads();

    float acc[R] = {0.f, 0.f, 0.f, 0.f};
    #pragma unroll 8
    for (int k = 0; k < DIM; k++) {
        float w = W[k * DIM + j];
        #pragma unroll
        for (int r = 0; r < R; r++) acc[r] += xs[r][k] * w;
    }

    float bj  = b[j];
    float a1j = a1[j];
    float a2j = a2[j];
    int lane = j & 31, warp = j >> 5;

    #pragma unroll
    for (int r = 0; r < R; r++) {
        int row = row0 + r;
        float v = acc[r] + bj;
        if (row < n) Wh[row * DIM + j] = v;
        float p1 = v * a1j;
        float p2 = v * a2j;
        #pragma unroll
        for (int o = 16; o > 0; o >>= 1) {
            p1 += __shfl_down_sync(0xFFFFFFFFu, p1, o);
            p2 += __shfl_down_sync(0xFFFFFFFFu, p2, o);
        }
        if (lane == 0) { red[r][warp] = p1; red[R + r][warp] = p2; }
    }
    __syncthreads();

    if (j < 2 * R) {
        float t = red[j][0] + red[j][1] + red[j][2] + red[j][3];
        int r   = j & (R - 1);
        int row = row0 + r;
        if (row < n) {
            if (j < R) s1[row] = t;
            else       s2[row] = t;
        }
    }
}

// ---------------- edge pass 1: segment max ----------------------------------
__global__ void edge_max_kernel(const int* __restrict__ src,
                                const int* __restrict__ dst,
                                const float* __restrict__ el,
                                const float* __restrict__ er,
                                float* __restrict__ m)
{
    int i = blockIdx.x * blockDim.x + threadIdx.x;
    if (i >= NEDGE) return;
    float e = leaky(el[src[i]] + er[dst[i]]);
    atomicMaxFloat(&m[dst[i]], e);
}

// ---------------- edge pass 2: softmax denominator --------------------------
__global__ void edge_sum_kernel(const int* __restrict__ src,
                                const int* __restrict__ dst,
                                const float* __restrict__ el,
                                const float* __restrict__ er,
                                const float* __restrict__ m,
                                float* __restrict__ s)
{
    int i = blockIdx.x * blockDim.x + threadIdx.x;
    if (i >= NEDGE) return;
    int di  = dst[i];
    float e = leaky(el[src[i]] + er[di]);
    atomicAdd(&s[di], expf(e - m[di]));
}

// ---------------- edge pass 3: weighted aggregation -------------------------
// one warp per edge; each lane handles 4 contiguous floats (float4 gather)
__global__ void __launch_bounds__(256) edge_aggr_kernel(
    const int* __restrict__ src, const int* __restrict__ dst,
    const float* __restrict__ el, const float* __restrict__ er,
    const float* __restrict__ m, const float* __restrict__ s,
    const float* __restrict__ Wh, float* __restrict__ out)
{
    int gtid = blockIdx.x * blockDim.x + threadIdx.x;
    int wid  = gtid >> 5;
    int lane = gtid & 31;
    if (wid >= NEDGE) return;

    int si = src[wid];
    int di = dst[wid];
    float e     = leaky(el[si] + er[di]);
    float alpha = expf(e - m[di]) / s[di];

    float4 v = ((const float4*)(Wh + (size_t)si * DIM))[lane];
    float* o = out + (size_t)di * DIM + lane * 4;
    atomicAdd(o + 0, alpha * v.x);
    atomicAdd(o + 1, alpha * v.y);
    atomicAdd(o + 2, alpha * v.z);
    atomicAdd(o + 3, alpha * v.w);
}

// ---------------- launch -----------------------------------------------------
extern "C" void kernel_launch(void* const* d_in, const int* in_sizes, int n_in,
                              void* d_out, int out_size)
{
    const float* feat_drug    = (const float*)d_in[0];
    const float* feat_disease = (const float*)d_in[1];
    const float* W_ind = (const float*)d_in[2];
    const float* b_ind = (const float*)d_in[3];
    const float* a_ind = (const float*)d_in[4];
    const float* W_rev = (const float*)d_in[5];
    const float* b_rev = (const float*)d_in[6];
    const float* a_rev = (const float*)d_in[7];
    const float* W_dd  = (const float*)d_in[8];
    const float* b_dd  = (const float*)d_in[9];
    const float* a_dd  = (const float*)d_in[10];
    const int* src_ind = (const int*)d_in[11];
    const int* dst_ind = (const int*)d_in[12];
    const int* src_rev = (const int*)d_in[13];
    const int* dst_rev = (const int*)d_in[14];
    const int* src_dd  = (const int*)d_in[15];
    const int* dst_dd  = (const int*)d_in[16];

    float* out = (float*)d_out;                 // [h_drug (20000*128) | h_disease (20000*128)]
    float* h_drug = out;
    float* h_dis  = out + (size_t)N_DRUG * DIM;

    // scratch symbol addresses
    float *Wh_ind, *Wh_rev, *Wh_dd;
    float *el_ind, *er_rev, *el_rev, *er_ind, *el_dd, *er_dd;
    float *mptr, *sptr;
    cudaGetSymbolAddress((void**)&Wh_ind, g_Wh_ind);
    cudaGetSymbolAddress((void**)&Wh_rev, g_Wh_rev);
    cudaGetSymbolAddress((void**)&Wh_dd,  g_Wh_dd);
    cudaGetSymbolAddress((void**)&el_ind, g_el_ind);
    cudaGetSymbolAddress((void**)&er_rev, g_er_rev);
    cudaGetSymbolAddress((void**)&el_rev, g_el_rev);
    cudaGetSymbolAddress((void**)&er_ind, g_er_ind);
    cudaGetSymbolAddress((void**)&el_dd,  g_el_dd);
    cudaGetSymbolAddress((void**)&er_dd,  g_er_dd);
    cudaGetSymbolAddress((void**)&mptr,   g_m);
    cudaGetSymbolAddress((void**)&sptr,   g_s);

    float* m_ind = mptr + 0 * N_DIS;
    float* m_rev = mptr + 1 * N_DIS;
    float* m_dd  = mptr + 2 * N_DIS;
    float* s_ind = sptr + 0 * N_DIS;
    float* s_rev = sptr + 1 * N_DIS;
    float* s_dd  = sptr + 2 * N_DIS;

    // 1. init output + m/s
    int init_total = out_size + 6 * N_DIS;
    init_kernel<<<(init_total + 255) / 256, 256>>>(out, out_size);

    // 2. fused GEMM + projections
    //    ind-src / rev-dstkey live on Wh_ind; rev-src / ind-dstkey on Wh_rev
    gemm_proj_kernel<<<(N_DRUG + 3) / 4, 128>>>(feat_drug,    W_ind, b_ind,
                                                a_ind,        a_rev + DIM,
                                                Wh_ind, el_ind, er_rev, N_DRUG);
    gemm_proj_kernel<<<(N_DIS + 3) / 4, 128>>>(feat_disease,  W_rev, b_rev,
                                                a_rev,        a_ind + DIM,
                                                Wh_rev, el_rev, er_ind, N_DIS);
    gemm_proj_kernel<<<(N_DIS + 3) / 4, 128>>>(feat_disease,  W_dd,  b_dd,
                                                a_dd,         a_dd + DIM,
                                                Wh_dd, el_dd, er_dd, N_DIS);

    int eb = (NEDGE + 255) / 256;

    // 3. segment max (per etype)
    edge_max_kernel<<<eb, 256>>>(src_ind, dst_ind, el_ind, er_ind, m_ind);
    edge_max_kernel<<<eb, 256>>>(src_rev, dst_rev, el_rev, er_rev, m_rev);
    edge_max_kernel<<<eb, 256>>>(src_dd,  dst_dd,  el_dd,  er_dd,  m_dd);

    // 4. softmax denominators
    edge_sum_kernel<<<eb, 256>>>(src_ind, dst_ind, el_ind, er_ind, m_ind, s_ind);
    edge_sum_kernel<<<eb, 256>>>(src_rev, dst_rev, el_rev, er_rev, m_rev, s_rev);
    edge_sum_kernel<<<eb, 256>>>(src_dd,  dst_dd,  el_dd,  er_dd,  m_dd,  s_dd);

    // 5. weighted aggregation (warp per edge)
    int ab = (NEDGE * 32 + 255) / 256;
    edge_aggr_kernel<<<ab, 256>>>(src_ind, dst_ind, el_ind, er_ind, m_ind, s_ind,
                                  Wh_ind, h_dis);
    edge_aggr_kernel<<<ab, 256>>>(src_rev, dst_rev, el_rev, er_rev, m_rev, s_rev,
                                  Wh_rev, h_drug);
    edge_aggr_kernel<<<ab, 256>>>(src_dd,  dst_dd,  el_dd,  er_dd,  m_dd,  s_dd,
                                  Wh_dd, h_dis);
}

// round 2
// speedup vs baseline: 1.2036x; 1.2036x over previous
#include <cuda_runtime.h>
#include <math.h>

#define N_DRUG 20000
#define N_DIS  20000
#define NEDGE  300000
#define DIM    128

// ---------------- scratch (device globals; no allocation allowed) ----------
__device__ float g_Wh_ind[N_DRUG * DIM];
__device__ float g_Wh_rev[N_DIS * DIM];
__device__ float g_Wh_dd [N_DIS * DIM];

__device__ float g_el_ind[N_DRUG];
__device__ float g_er_rev[N_DRUG];
__device__ float g_el_rev[N_DIS];
__device__ float g_er_ind[N_DIS];
__device__ float g_el_dd [N_DIS];
__device__ float g_er_dd [N_DIS];

__device__ float g_m[3][N_DIS];     // per-etype segment max
__device__ float g_s[3][N_DIS];     // per-etype softmax denom
__device__ float g_e[3][NEDGE];     // per-edge logit, then exp(e-m)

// ---------------- param structs ---------------------------------------------
struct GemmArgs {
    const float* X[3];
    const float* W[3];
    const float* b[3];
    const float* a1[3];
    const float* a2[3];
    float* Wh[3];
    float* s1[3];
    float* s2[3];
};

struct EdgeArgs {
    const int*   src[3];
    const int*   dst[3];
    const float* el[3];
    const float* er[3];
    float*       m[3];
    float*       s[3];
    float*       e[3];
    const float* Wh[3];
    float*       out[3];
};

// ---------------- helpers ----------------------------------------------------
__device__ __forceinline__ void atomicMaxFloat(float* addr, float val) {
    if (val >= 0.0f) atomicMax((int*)addr, __float_as_int(val));
    else             atomicMin((unsigned int*)addr, __float_as_uint(val));
}

__device__ __forceinline__ float leaky(float x) {
    return x > 0.0f ? x : 0.01f * x;
}

__device__ __forceinline__ void red_add_v4(float* addr, float4 v) {
    asm volatile("red.global.add.v4.f32 [%0], {%1,%2,%3,%4};"
                 :: "l"(addr), "f"(v.x), "f"(v.y), "f"(v.z), "f"(v.w)
                 : "memory");
}

// ---------------- init: m = -inf, s = 0 --------------------------------------
__global__ void init_kernel() {
    int i = blockIdx.x * blockDim.x + threadIdx.x;
    if (i < 3 * N_DIS)          (&g_m[0][0])[i] = -INFINITY;
    else if (i < 6 * N_DIS)     (&g_s[0][0])[i - 3 * N_DIS] = 0.0f;
}

// ---------------- fused GEMM + bias + attention scalar projections ----------
// 8 rows/block, 128 threads (one output column each), 3 etypes via blockIdx.y.
// 20000 % 8 == 0 so no row-bound checks needed.
__global__ void __launch_bounds__(128) gemm_proj_kernel(GemmArgs ga) {
    const int R = 8;
    const int t = blockIdx.y;
    const float* __restrict__ X  = ga.X[t];
    const float* __restrict__ W  = ga.W[t];

    __shared__ float xs[R][DIM];
    __shared__ float red[2 * R][4];

    int j    = threadIdx.x;
    int row0 = blockIdx.x * R;

    #pragma unroll
    for (int r = 0; r < R; r++)
        xs[r][j] = X[(size_t)(row0 + r) * DIM + j];
    __syncthreads();

    float acc[R] = {0.f, 0.f, 0.f, 0.f, 0.f, 0.f, 0.f, 0.f};
    #pragma unroll 4
    for (int k = 0; k < DIM; k += 4) {
        float w0 = W[(k + 0) * DIM + j];
        float w1 = W[(k + 1) * DIM + j];
        float w2 = W[(k + 2) * DIM + j];
        float w3 = W[(k + 3) * DIM + j];
        #pragma unroll
        for (int r = 0; r < R; r++) {
            float4 x4 = *(const float4*)&xs[r][k];
            acc[r] += x4.x * w0;
            acc[r] += x4.y * w1;
            acc[r] += x4.z * w2;
            acc[r] += x4.w * w3;
        }
    }

    float bj  = ga.b[t][j];
    float a1j = ga.a1[t][j];
    float a2j = ga.a2[t][j];
    float* __restrict__ Wh = ga.Wh[t];
    int lane = j & 31, warp = j >> 5;

    #pragma unroll
    for (int r = 0; r < R; r++) {
        float v = acc[r] + bj;
        Wh[(size_t)(row0 + r) * DIM + j] = v;
        float p1 = v * a1j;
        float p2 = v * a2j;
        #pragma unroll
        for (int o = 16; o > 0; o >>= 1) {
            p1 += __shfl_down_sync(0xFFFFFFFFu, p1, o);
            p2 += __shfl_down_sync(0xFFFFFFFFu, p2, o);
        }
        if (lane == 0) { red[r][warp] = p1; red[R + r][warp] = p2; }
    }
    __syncthreads();

    if (j < 2 * R) {
        float tsum = red[j][0] + red[j][1] + red[j][2] + red[j][3];
        int r = j & (R - 1);
        if (j < R) ga.s1[t][row0 + r] = tsum;
        else       ga.s2[t][row0 + r] = tsum;
    }
}

// ---------------- edge pass 1: logit + segment max (all 3 etypes) -----------
__global__ void edge_max_kernel(EdgeArgs ea) {
    int t = blockIdx.y;
    int i = blockIdx.x * blockDim.x + threadIdx.x;
    if (i >= NEDGE) return;
    int si = ea.src[t][i];
    int di = ea.dst[t][i];
    float e = leaky(ea.el[t][si] + ea.er[t][di]);
    ea.e[t][i] = e;
    atomicMaxFloat(&ea.m[t][di], e);
}

// ---------------- edge pass 2: p = exp(e-m), denom sum ----------------------
__global__ void edge_sum_kernel(EdgeArgs ea) {
    int t = blockIdx.y;
    int i = blockIdx.x * blockDim.x + threadIdx.x;
    if (i >= NEDGE) return;
    int di = ea.dst[t][i];
    float p = expf(ea.e[t][i] - ea.m[t][di]);
    ea.e[t][i] = p;
    atomicAdd(&ea.s[t][di], p);
}

// ---------------- edge pass 3: weighted aggregation (all 3 etypes) ----------
// warp per edge; lane handles 4 contiguous floats; vectorized red.v4.f32
__global__ void __launch_bounds__(256) edge_aggr_kernel(EdgeArgs ea) {
    int t    = blockIdx.y;
    int gtid = blockIdx.x * blockDim.x + threadIdx.x;
    int wid  = gtid >> 5;
    int lane = gtid & 31;
    if (wid >= NEDGE) return;

    int si = 0, di = 0;
    float alpha = 0.f;
    if (lane == 0) {
        si = ea.src[t][wid];
        di = ea.dst[t][wid];
        alpha = ea.e[t][wid] / ea.s[t][di];
    }
    si    = __shfl_sync(0xFFFFFFFFu, si, 0);
    di    = __shfl_sync(0xFFFFFFFFu, di, 0);
    alpha = __shfl_sync(0xFFFFFFFFu, alpha, 0);

    float4 v = ((const float4*)(ea.Wh[t] + (size_t)si * DIM))[lane];
    float4 msg = make_float4(alpha * v.x, alpha * v.y, alpha * v.z, alpha * v.w);
    red_add_v4(ea.out[t] + (size_t)di * DIM + lane * 4, msg);
}

// ---------------- launch -----------------------------------------------------
extern "C" void kernel_launch(void* const* d_in, const int* in_sizes, int n_in,
                              void* d_out, int out_size)
{
    const float* feat_drug    = (const float*)d_in[0];
    const float* feat_disease = (const float*)d_in[1];
    const float* W_ind = (const float*)d_in[2];
    const float* b_ind = (const float*)d_in[3];
    const float* a_ind = (const float*)d_in[4];
    const float* W_rev = (const float*)d_in[5];
    const float* b_rev = (const float*)d_in[6];
    const float* a_rev = (const float*)d_in[7];
    const float* W_dd  = (const float*)d_in[8];
    const float* b_dd  = (const float*)d_in[9];
    const float* a_dd  = (const float*)d_in[10];
    const int* src_ind = (const int*)d_in[11];
    const int* dst_ind = (const int*)d_in[12];
    const int* src_rev = (const int*)d_in[13];
    const int* dst_rev = (const int*)d_in[14];
    const int* src_dd  = (const int*)d_in[15];
    const int* dst_dd  = (const int*)d_in[16];

    float* out = (float*)d_out;
    float* h_drug = out;
    float* h_dis  = out + (size_t)N_DRUG * DIM;

    float *Wh_ind, *Wh_rev, *Wh_dd;
    float *el_ind, *er_rev, *el_rev, *er_ind, *el_dd, *er_dd;
    float *mptr, *sptr, *eptr;
    cudaGetSymbolAddress((void**)&Wh_ind, g_Wh_ind);
    cudaGetSymbolAddress((void**)&Wh_rev, g_Wh_rev);
    cudaGetSymbolAddress((void**)&Wh_dd,  g_Wh_dd);
    cudaGetSymbolAddress((void**)&el_ind, g_el_ind);
    cudaGetSymbolAddress((void**)&er_rev, g_er_rev);
    cudaGetSymbolAddress((void**)&el_rev, g_el_rev);
    cudaGetSymbolAddress((void**)&er_ind, g_er_ind);
    cudaGetSymbolAddress((void**)&el_dd,  g_el_dd);
    cudaGetSymbolAddress((void**)&er_dd,  g_er_dd);
    cudaGetSymbolAddress((void**)&mptr,   g_m);
    cudaGetSymbolAddress((void**)&sptr,   g_s);
    cudaGetSymbolAddress((void**)&eptr,   g_e);

    // zero output (memset node is graph-capturable)
    cudaMemsetAsync(d_out, 0, (size_t)out_size * sizeof(float), 0);
    init_kernel<<<(6 * N_DIS + 255) / 256, 256>>>();

    // batched GEMM: etype 0=ind(drug), 1=rev(disease), 2=dd(disease)
    GemmArgs ga;
    ga.X[0] = feat_drug;    ga.W[0] = W_ind; ga.b[0] = b_ind;
    ga.a1[0] = a_ind;       ga.a2[0] = a_rev + DIM;
    ga.Wh[0] = Wh_ind;      ga.s1[0] = el_ind; ga.s2[0] = er_rev;

    ga.X[1] = feat_disease; ga.W[1] = W_rev; ga.b[1] = b_rev;
    ga.a1[1] = a_rev;       ga.a2[1] = a_ind + DIM;
    ga.Wh[1] = Wh_rev;      ga.s1[1] = el_rev; ga.s2[1] = er_ind;

    ga.X[2] = feat_disease; ga.W[2] = W_dd;  ga.b[2] = b_dd;
    ga.a1[2] = a_dd;        ga.a2[2] = a_dd + DIM;
    ga.Wh[2] = Wh_dd;       ga.s1[2] = el_dd; ga.s2[2] = er_dd;

    dim3 ggrid(N_DRUG / 8, 3);
    gemm_proj_kernel<<<ggrid, 128>>>(ga);

    // edge args: etype 0 = ind (drug->dis), 1 = rev (dis->drug), 2 = dd (dis->dis)
    EdgeArgs ea;
    ea.src[0] = src_ind; ea.dst[0] = dst_ind;
    ea.el[0] = el_ind;   ea.er[0] = er_ind;
    ea.m[0] = mptr + 0 * N_DIS; ea.s[0] = sptr + 0 * N_DIS;
    ea.e[0] = eptr + 0 * NEDGE;
    ea.Wh[0] = Wh_ind;   ea.out[0] = h_dis;

    ea.src[1] = src_rev; ea.dst[1] = dst_rev;
    ea.el[1] = el_rev;   ea.er[1] = er_rev;
    ea.m[1] = mptr + 1 * N_DIS; ea.s[1] = sptr + 1 * N_DIS;
    ea.e[1] = eptr + 1 * NEDGE;
    ea.Wh[1] = Wh_rev;   ea.out[1] = h_drug;

    ea.src[2] = src_dd;  ea.dst[2] = dst_dd;
    ea.el[2] = el_dd;    ea.er[2] = er_dd;
    ea.m[2] = mptr + 2 * N_DIS; ea.s[2] = sptr + 2 * N_DIS;
    ea.e[2] = eptr + 2 * NEDGE;
    ea.Wh[2] = Wh_dd;    ea.out[2] = h_dis;

    dim3 egrid((NEDGE + 255) / 256, 3);
    edge_max_kernel<<<egrid, 256>>>(ea);
    edge_sum_kernel<<<egrid, 256>>>(ea);

    dim3 agrid((NEDGE * 32 + 255) / 256, 3);
    edge_aggr_kernel<<<agrid, 256>>>(ea);
}

// round 3
// speedup vs baseline: 2.1049x; 1.7488x over previous
#include <cuda_runtime.h>
#include <math.h>

#define N_DRUG 20000
#define N_DIS  20000
#define NEDGE  300000
#define DIM    128

// ---------------- scratch (device globals; no allocation allowed) ----------
__device__ float g_Wh_ind[N_DRUG * DIM];
__device__ float g_Wh_rev[N_DIS * DIM];
__device__ float g_Wh_dd [N_DIS * DIM];

__device__ float g_el_ind[N_DRUG];
__device__ float g_er_rev[N_DRUG];
__device__ float g_el_rev[N_DIS];
__device__ float g_er_ind[N_DIS];
__device__ float g_el_dd [N_DIS];
__device__ float g_er_dd [N_DIS];

__device__ int   g_deg[3][N_DIS];        // per-etype in-degree
__device__ int   g_off[3][N_DIS + 1];    // CSR offsets
__device__ int   g_cur[3][N_DIS];        // scatter cursors
__device__ int   g_src_s[3][NEDGE];      // dst-sorted src ids
__device__ float g_e_s  [3][NEDGE];      // dst-sorted edge logits

// ---------------- param structs ---------------------------------------------
struct GemmArgs {
    const float* X[3];
    const float* W[3];
    const float* b[3];
    const float* a1[3];
    const float* a2[3];
    float* Wh[3];
    float* s1[3];
    float* s2[3];
};

struct EdgeIdx {
    const int* src[3];
    const int* dst[3];
};

// ---------------- helpers ----------------------------------------------------
__device__ __forceinline__ float leaky(float x) {
    return x > 0.0f ? x : 0.01f * x;
}

// ---------------- init: deg = 0 ----------------------------------------------
__global__ void init_deg_kernel() {
    int i = blockIdx.x * blockDim.x + threadIdx.x;
    if (i < 3 * N_DIS) (&g_deg[0][0])[i] = 0;
}

// ---------------- fused GEMM + bias + attention scalar projections ----------
__global__ void __launch_bounds__(128) gemm_proj_kernel(GemmArgs ga) {
    const int R = 8;
    const int t = blockIdx.y;
    const float* __restrict__ X = ga.X[t];
    const float* __restrict__ W = ga.W[t];

    __shared__ float xs[R][DIM];
    __shared__ float red[2 * R][4];

    int j    = threadIdx.x;
    int row0 = blockIdx.x * R;

    #pragma unroll
    for (int r = 0; r < R; r++)
        xs[r][j] = X[(size_t)(row0 + r) * DIM + j];
    __syncthreads();

    float acc[R] = {0.f, 0.f, 0.f, 0.f, 0.f, 0.f, 0.f, 0.f};
    #pragma unroll 4
    for (int k = 0; k < DIM; k += 4) {
        float w0 = W[(k + 0) * DIM + j];
        float w1 = W[(k + 1) * DIM + j];
        float w2 = W[(k + 2) * DIM + j];
        float w3 = W[(k + 3) * DIM + j];
        #pragma unroll
        for (int r = 0; r < R; r++) {
            float4 x4 = *(const float4*)&xs[r][k];
            acc[r] += x4.x * w0;
            acc[r] += x4.y * w1;
            acc[r] += x4.z * w2;
            acc[r] += x4.w * w3;
        }
    }

    float bj  = ga.b[t][j];
    float a1j = ga.a1[t][j];
    float a2j = ga.a2[t][j];
    float* __restrict__ Wh = ga.Wh[t];
    int lane = j & 31, warp = j >> 5;

    #pragma unroll
    for (int r = 0; r < R; r++) {
        float v = acc[r] + bj;
        Wh[(size_t)(row0 + r) * DIM + j] = v;
        float p1 = v * a1j;
        float p2 = v * a2j;
        #pragma unroll
        for (int o = 16; o > 0; o >>= 1) {
            p1 += __shfl_down_sync(0xFFFFFFFFu, p1, o);
            p2 += __shfl_down_sync(0xFFFFFFFFu, p2, o);
        }
        if (lane == 0) { red[r][warp] = p1; red[R + r][warp] = p2; }
    }
    __syncthreads();

    if (j < 2 * R) {
        float tsum = red[j][0] + red[j][1] + red[j][2] + red[j][3];
        int r = j & (R - 1);
        if (j < R) ga.s1[t][row0 + r] = tsum;
        else       ga.s2[t][row0 + r] = tsum;
    }
}

// ---------------- histogram ---------------------------------------------------
__global__ void hist_kernel(EdgeIdx ei) {
    int t = blockIdx.y;
    int i = blockIdx.x * blockDim.x + threadIdx.x;
    if (i >= NEDGE) return;
    atomicAdd(&g_deg[t][ei.dst[t][i]], 1);
}

// ---------------- exclusive scan (one block per etype) -----------------------
__global__ void __launch_bounds__(1024) scan_kernel() {
    const int VPT = 20;                       // 1024*20 >= 20000
    int t   = blockIdx.x;
    int tid = threadIdx.x;
    int base = tid * VPT;

    int local[VPT];
    int sum = 0;
    #pragma unroll
    for (int i = 0; i < VPT; i++) {
        int idx = base + i;
        int v = (idx < N_DIS) ? g_deg[t][idx] : 0;
        local[i] = sum;
        sum += v;
    }

    int lane = tid & 31, wid = tid >> 5;
    int x = sum;
    #pragma unroll
    for (int o = 1; o < 32; o <<= 1) {
        int y = __shfl_up_sync(0xFFFFFFFFu, x, o);
        if (lane >= o) x += y;
    }
    __shared__ int wsum[32];
    if (lane == 31) wsum[wid] = x;
    __syncthreads();
    if (wid == 0) {
        int w = wsum[lane];
        #pragma unroll
        for (int o = 1; o < 32; o <<= 1) {
            int y = __shfl_up_sync(0xFFFFFFFFu, w, o);
            if (lane >= o) w += y;
        }
        wsum[lane] = w;
    }
    __syncthreads();
    int warpbase = (wid > 0) ? wsum[wid - 1] : 0;
    int tbase    = warpbase + x - sum;        // exclusive prefix for this thread

    #pragma unroll
    for (int i = 0; i < VPT; i++) {
        int idx = base + i;
        if (idx < N_DIS) {
            int o = tbase + local[i];
            g_off[t][idx] = o;
            g_cur[t][idx] = o;
        }
    }
    if (tid == 0) g_off[t][N_DIS] = NEDGE;
}

// ---------------- scatter: build sorted (src, logit) lists -------------------
__global__ void scatter_kernel(EdgeIdx ei) {
    int t = blockIdx.y;
    int i = blockIdx.x * blockDim.x + threadIdx.x;
    if (i >= NEDGE) return;
    const float* el_tab[3] = {g_el_ind, g_el_rev, g_el_dd};
    const float* er_tab[3] = {g_er_ind, g_er_rev, g_er_dd};
    int si = ei.src[t][i];
    int di = ei.dst[t][i];
    float e = leaky(el_tab[t][si] + er_tab[t][di]);
    int pos = atomicAdd(&g_cur[t][di], 1);
    g_src_s[t][pos] = si;
    g_e_s[t][pos]   = e;
}

// ---------------- per-dst softmax + aggregation (warp per dst node) ----------
__device__ __forceinline__ void agg_etype(int t, int d, int lane,
                                          const float4* __restrict__ Wh,
                                          float4& acc)
{
    int lo = g_off[t][d];
    int hi = g_off[t][d + 1];
    if (hi <= lo) return;

    float mx = -INFINITY;
    for (int k = lo + lane; k < hi; k += 32)
        mx = fmaxf(mx, g_e_s[t][k]);
    #pragma unroll
    for (int o = 16; o > 0; o >>= 1)
        mx = fmaxf(mx, __shfl_xor_sync(0xFFFFFFFFu, mx, o));

    float sm = 0.f;
    for (int k = lo + lane; k < hi; k += 32)
        sm += __expf(g_e_s[t][k] - mx);
    #pragma unroll
    for (int o = 16; o > 0; o >>= 1)
        sm += __shfl_xor_sync(0xFFFFFFFFu, sm, o);
    float inv = 1.0f / sm;

    #pragma unroll 4
    for (int k = lo; k < hi; k++) {
        int s   = g_src_s[t][k];
        float p = __expf(g_e_s[t][k] - mx) * inv;
        float4 v = Wh[(size_t)s * 32 + lane];
        acc.x += p * v.x;
        acc.y += p * v.y;
        acc.z += p * v.z;
        acc.w += p * v.w;
    }
}

__global__ void __launch_bounds__(256) aggr_kernel(float* __restrict__ h_drug,
                                                   float* __restrict__ h_dis)
{
    int gw   = (blockIdx.x * blockDim.x + threadIdx.x) >> 5;
    int lane = threadIdx.x & 31;
    float4 acc = make_float4(0.f, 0.f, 0.f, 0.f);

    if (gw < N_DRUG) {
        agg_etype(1, gw, lane, (const float4*)g_Wh_rev, acc);
        ((float4*)(h_drug + (size_t)gw * DIM))[lane] = acc;
    } else if (gw < N_DRUG + N_DIS) {
        int d = gw - N_DRUG;
        agg_etype(0, d, lane, (const float4*)g_Wh_ind, acc);
        agg_etype(2, d, lane, (const float4*)g_Wh_dd,  acc);
        ((float4*)(h_dis + (size_t)d * DIM))[lane] = acc;
    }
}

// ---------------- launch -----------------------------------------------------
extern "C" void kernel_launch(void* const* d_in, const int* in_sizes, int n_in,
                              void* d_out, int out_size)
{
    const float* feat_drug    = (const float*)d_in[0];
    const float* feat_disease = (const float*)d_in[1];
    const float* W_ind = (const float*)d_in[2];
    const float* b_ind = (const float*)d_in[3];
    const float* a_ind = (const float*)d_in[4];
    const float* W_rev = (const float*)d_in[5];
    const float* b_rev = (const float*)d_in[6];
    const float* a_rev = (const float*)d_in[7];
    const float* W_dd  = (const float*)d_in[8];
    const float* b_dd  = (const float*)d_in[9];
    const float* a_dd  = (const float*)d_in[10];
    const int* src_ind = (const int*)d_in[11];
    const int* dst_ind = (const int*)d_in[12];
    const int* src_rev = (const int*)d_in[13];
    const int* dst_rev = (const int*)d_in[14];
    const int* src_dd  = (const int*)d_in[15];
    const int* dst_dd  = (const int*)d_in[16];

    float* out    = (float*)d_out;
    float* h_drug = out;
    float* h_dis  = out + (size_t)N_DRUG * DIM;

    float *Wh_ind, *Wh_rev, *Wh_dd;
    float *el_ind, *er_rev, *el_rev, *er_ind, *el_dd, *er_dd;
    cudaGetSymbolAddress((void**)&Wh_ind, g_Wh_ind);
    cudaGetSymbolAddress((void**)&Wh_rev, g_Wh_rev);
    cudaGetSymbolAddress((void**)&Wh_dd,  g_Wh_dd);
    cudaGetSymbolAddress((void**)&el_ind, g_el_ind);
    cudaGetSymbolAddress((void**)&er_rev, g_er_rev);
    cudaGetSymbolAddress((void**)&el_rev, g_el_rev);
    cudaGetSymbolAddress((void**)&er_ind, g_er_ind);
    cudaGetSymbolAddress((void**)&el_dd,  g_el_dd);
    cudaGetSymbolAddress((void**)&er_dd,  g_er_dd);

    // 1. zero degree counters
    init_deg_kernel<<<(3 * N_DIS + 255) / 256, 256>>>();

    // 2. batched fused GEMM + projections
    GemmArgs ga;
    ga.X[0] = feat_drug;    ga.W[0] = W_ind; ga.b[0] = b_ind;
    ga.a1[0] = a_ind;       ga.a2[0] = a_rev + DIM;
    ga.Wh[0] = Wh_ind;      ga.s1[0] = el_ind; ga.s2[0] = er_rev;

    ga.X[1] = feat_disease; ga.W[1] = W_rev; ga.b[1] = b_rev;
    ga.a1[1] = a_rev;       ga.a2[1] = a_ind + DIM;
    ga.Wh[1] = Wh_rev;      ga.s1[1] = el_rev; ga.s2[1] = er_ind;

    ga.X[2] = feat_disease; ga.W[2] = W_dd;  ga.b[2] = b_dd;
    ga.a1[2] = a_dd;        ga.a2[2] = a_dd + DIM;
    ga.Wh[2] = Wh_dd;       ga.s1[2] = el_dd; ga.s2[2] = er_dd;

    dim3 ggrid(N_DRUG / 8, 3);
    gemm_proj_kernel<<<ggrid, 128>>>(ga);

    // etype 0 = ind (drug->dis), 1 = rev (dis->drug), 2 = dd (dis->dis)
    EdgeIdx ei;
    ei.src[0] = src_ind; ei.dst[0] = dst_ind;
    ei.src[1] = src_rev; ei.dst[1] = dst_rev;
    ei.src[2] = src_dd;  ei.dst[2] = dst_dd;

    dim3 egrid((NEDGE + 255) / 256, 3);

    // 3. CSR build: histogram -> scan -> scatter (with logit precompute)
    hist_kernel<<<egrid, 256>>>(ei);
    scan_kernel<<<3, 1024>>>();
    scatter_kernel<<<egrid, 256>>>(ei);

    // 4. per-dst softmax + aggregation, one warp per dst node
    int total_warps = N_DRUG + N_DIS;
    int ablocks = (total_warps * 32 + 255) / 256;
    aggr_kernel<<<ablocks, 256>>>(h_drug, h_dis);
}

// round 4
// speedup vs baseline: 2.3639x; 1.1231x over previous
#include <cuda_runtime.h>
#include <cuda_fp16.h>
#include <math.h>

#define N_DRUG 20000
#define N_DIS  20000
#define NEDGE  300000
#define DIM    128

#define SCAN_ELEMS 1024                       // elements per scan block
#define SCAN_NB    ((N_DIS + SCAN_ELEMS - 1) / SCAN_ELEMS)   // 20
#define OFF_STRIDE (N_DIS + 4)                // keep rows 16B-aligned

// ---------------- scratch (device globals; no allocation allowed) ----------
__device__ __half g_Whh[3][N_DIS * DIM];     // fp16 Wh per etype (gather source)

__device__ float g_el_ind[N_DRUG];
__device__ float g_er_rev[N_DRUG];
__device__ float g_el_rev[N_DIS];
__device__ float g_er_ind[N_DIS];
__device__ float g_el_dd [N_DIS];
__device__ float g_er_dd [N_DIS];

__device__ int   g_deg[3][N_DIS];            // per-etype in-degree
__device__ int   g_off[3][OFF_STRIDE];       // CSR offsets (padded rows)
__device__ int   g_cur[3][N_DIS];            // scatter cursors
__device__ int   g_bsum[3][SCAN_NB];         // per-block partial sums
__device__ int   g_src_s[3][NEDGE];          // dst-sorted src ids
__device__ float g_e_s  [3][NEDGE];          // dst-sorted edge logits

// ---------------- param structs ---------------------------------------------
struct GemmArgs {
    const float* X[3];
    const float* W[3];
    const float* b[3];
    const float* a1[3];
    const float* a2[3];
    float* s1[3];
    float* s2[3];
};

struct EdgeIdx {
    const int* src[3];
    const int* dst[3];
};

// ---------------- helpers ----------------------------------------------------
__device__ __forceinline__ float leaky(float x) {
    return x > 0.0f ? x : 0.01f * x;
}

// ---------------- fused GEMM + bias + attention scalar projections ----------
// 8 rows/block, 128 threads (one output column each), 3 etypes via blockIdx.y.
__global__ void __launch_bounds__(128) gemm_proj_kernel(GemmArgs ga) {
    const int R = 8;
    const int t = blockIdx.y;
    const float* __restrict__ X = ga.X[t];
    const float* __restrict__ W = ga.W[t];

    __shared__ float xs[R][DIM];
    __shared__ float red[2 * R][4];

    int j    = threadIdx.x;
    int row0 = blockIdx.x * R;

    #pragma unroll
    for (int r = 0; r < R; r++)
        xs[r][j] = X[(size_t)(row0 + r) * DIM + j];
    __syncthreads();

    float acc[R] = {0.f, 0.f, 0.f, 0.f, 0.f, 0.f, 0.f, 0.f};
    #pragma unroll 4
    for (int k = 0; k < DIM; k += 4) {
        float w0 = W[(k + 0) * DIM + j];
        float w1 = W[(k + 1) * DIM + j];
        float w2 = W[(k + 2) * DIM + j];
        float w3 = W[(k + 3) * DIM + j];
        #pragma unroll
        for (int r = 0; r < R; r++) {
            float4 x4 = *(const float4*)&xs[r][k];
            acc[r] += x4.x * w0;
            acc[r] += x4.y * w1;
            acc[r] += x4.z * w2;
            acc[r] += x4.w * w3;
        }
    }

    float bj  = ga.b[t][j];
    float a1j = ga.a1[t][j];
    float a2j = ga.a2[t][j];
    __half* __restrict__ Whh = g_Whh[t];
    int lane = j & 31, warp = j >> 5;

    #pragma unroll
    for (int r = 0; r < R; r++) {
        float v = acc[r] + bj;
        Whh[(size_t)(row0 + r) * DIM + j] = __float2half(v);
        float p1 = v * a1j;
        float p2 = v * a2j;
        #pragma unroll
        for (int o = 16; o > 0; o >>= 1) {
            p1 += __shfl_down_sync(0xFFFFFFFFu, p1, o);
            p2 += __shfl_down_sync(0xFFFFFFFFu, p2, o);
        }
        if (lane == 0) { red[r][warp] = p1; red[R + r][warp] = p2; }
    }
    __syncthreads();

    if (j < 2 * R) {
        float tsum = red[j][0] + red[j][1] + red[j][2] + red[j][3];
        int r = j & (R - 1);
        if (j < R) ga.s1[t][row0 + r] = tsum;
        else       ga.s2[t][row0 + r] = tsum;
    }
}

// ---------------- histogram ---------------------------------------------------
__global__ void hist_kernel(EdgeIdx ei) {
    int t = blockIdx.y;
    int i = blockIdx.x * blockDim.x + threadIdx.x;
    if (i >= NEDGE) return;
    atomicAdd(&g_deg[t][ei.dst[t][i]], 1);
}

// ---------------- scan phase 1: per-block partial sums -----------------------
__global__ void __launch_bounds__(256) scan1_kernel() {
    int t   = blockIdx.y;
    int b   = blockIdx.x;
    int tid = threadIdx.x;
    int idx = b * SCAN_ELEMS + tid * 4;

    int4 v = (idx < N_DIS) ? *(const int4*)&g_deg[t][idx]
                           : make_int4(0, 0, 0, 0);
    int s = v.x + v.y + v.z + v.w;

    int lane = tid & 31, wid = tid >> 5;
    #pragma unroll
    for (int o = 16; o > 0; o >>= 1)
        s += __shfl_down_sync(0xFFFFFFFFu, s, o);

    __shared__ int ws[8];
    if (lane == 0) ws[wid] = s;
    __syncthreads();
    if (tid == 0) {
        int tot = 0;
        #pragma unroll
        for (int i = 0; i < 8; i++) tot += ws[i];
        g_bsum[t][b] = tot;
    }
}

// ---------------- scan phase 2: scan block partials (tiny) -------------------
__global__ void __launch_bounds__(96) scan2_kernel() {
    int tid  = threadIdx.x;
    int t    = tid >> 5;
    int lane = tid & 31;
    int v = (lane < SCAN_NB) ? g_bsum[t][lane] : 0;
    int x = v;
    #pragma unroll
    for (int o = 1; o < 32; o <<= 1) {
        int y = __shfl_up_sync(0xFFFFFFFFu, x, o);
        if (lane >= o) x += y;
    }
    if (lane < SCAN_NB) g_bsum[t][lane] = x - v;   // exclusive
    if (lane == 0)      g_off[t][N_DIS] = NEDGE;
}

// ---------------- scan phase 3: final offsets ---------------------------------
__global__ void __launch_bounds__(256) scan3_kernel() {
    int t   = blockIdx.y;
    int b   = blockIdx.x;
    int tid = threadIdx.x;
    int idx = b * SCAN_ELEMS + tid * 4;

    int4 v = (idx < N_DIS) ? *(const int4*)&g_deg[t][idx]
                           : make_int4(0, 0, 0, 0);
    int s = v.x + v.y + v.z + v.w;

    int lane = tid & 31, wid = tid >> 5;
    int x = s;
    #pragma unroll
    for (int o = 1; o < 32; o <<= 1) {
        int y = __shfl_up_sync(0xFFFFFFFFu, x, o);
        if (lane >= o) x += y;
    }
    __shared__ int ws[8];
    if (lane == 31) ws[wid] = x;
    __syncthreads();
    if (wid == 0 && lane < 8) {
        int w = ws[lane];
        #pragma unroll
        for (int o = 1; o < 8; o <<= 1) {
            int y = __shfl_up_sync(0xFFu, w, o);
            if (lane >= o) w += y;
        }
        ws[lane] = w;
    }
    __syncthreads();

    int blockExcl = ((wid > 0) ? ws[wid - 1] : 0) + (x - s);
    int base = g_bsum[t][b] + blockExcl;

    if (idx < N_DIS) {
        int4 o;
        o.x = base;
        o.y = o.x + v.x;
        o.z = o.y + v.y;
        o.w = o.z + v.z;
        *(int4*)&g_off[t][idx] = o;
        *(int4*)&g_cur[t][idx] = o;
    }
}

// ---------------- scatter: build dst-sorted (src, logit) lists ---------------
__global__ void scatter_kernel(EdgeIdx ei) {
    int t = blockIdx.y;
    int i = blockIdx.x * blockDim.x + threadIdx.x;
    if (i >= NEDGE) return;
    const float* el_tab[3] = {g_el_ind, g_el_rev, g_el_dd};
    const float* er_tab[3] = {g_er_ind, g_er_rev, g_er_dd};
    int si = ei.src[t][i];
    int di = ei.dst[t][i];
    float e = leaky(el_tab[t][si] + er_tab[t][di]);
    int pos = atomicAdd(&g_cur[t][di], 1);
    g_src_s[t][pos] = si;
    g_e_s[t][pos]   = e;
}

// ---------------- per-dst softmax + aggregation (warp per dst node) ----------
__device__ __forceinline__ void agg_etype(int t, int d, int lane, float4& acc)
{
    const __half* __restrict__ Wh = g_Whh[t];
    int lo = g_off[t][d];
    int hi = g_off[t][d + 1];
    if (hi <= lo) return;

    float mx = -INFINITY;
    for (int k = lo + lane; k < hi; k += 32)
        mx = fmaxf(mx, g_e_s[t][k]);
    #pragma unroll
    for (int o = 16; o > 0; o >>= 1)
        mx = fmaxf(mx, __shfl_xor_sync(0xFFFFFFFFu, mx, o));

    float sm = 0.f;
    for (int k = lo + lane; k < hi; k += 32)
        sm += __expf(g_e_s[t][k] - mx);
    #pragma unroll
    for (int o = 16; o > 0; o >>= 1)
        sm += __shfl_xor_sync(0xFFFFFFFFu, sm, o);
    float inv = 1.0f / sm;

    for (int base = lo; base < hi; base += 32) {
        int n = min(32, hi - base);
        int   s = 0;
        float p = 0.f;
        if (lane < n) {
            s = g_src_s[t][base + lane];
            p = __expf(g_e_s[t][base + lane] - mx) * inv;
        }
        #pragma unroll 4
        for (int j = 0; j < n; j++) {
            int   sj = __shfl_sync(0xFFFFFFFFu, s, j);
            float pj = __shfl_sync(0xFFFFFFFFu, p, j);
            uint2 u = ((const uint2*)(Wh + (size_t)sj * DIM))[lane];
            __half2 h0 = *(__half2*)&u.x;
            __half2 h1 = *(__half2*)&u.y;
            float2 f0 = __half22float2(h0);
            float2 f1 = __half22float2(h1);
            acc.x += pj * f0.x;
            acc.y += pj * f0.y;
            acc.z += pj * f1.x;
            acc.w += pj * f1.y;
        }
    }
}

__global__ void __launch_bounds__(256) aggr_kernel(float* __restrict__ h_drug,
                                                   float* __restrict__ h_dis)
{
    int gw   = (blockIdx.x * blockDim.x + threadIdx.x) >> 5;
    int lane = threadIdx.x & 31;
    float4 acc = make_float4(0.f, 0.f, 0.f, 0.f);

    if (gw < N_DRUG) {
        agg_etype(1, gw, lane, acc);
        ((float4*)(h_drug + (size_t)gw * DIM))[lane] = acc;
    } else if (gw < N_DRUG + N_DIS) {
        int d = gw - N_DRUG;
        agg_etype(0, d, lane, acc);
        agg_etype(2, d, lane, acc);
        ((float4*)(h_dis + (size_t)d * DIM))[lane] = acc;
    }
}

// ---------------- launch -----------------------------------------------------
extern "C" void kernel_launch(void* const* d_in, const int* in_sizes, int n_in,
                              void* d_out, int out_size)
{
    const float* feat_drug    = (const float*)d_in[0];
    const float* feat_disease = (const float*)d_in[1];
    const float* W_ind = (const float*)d_in[2];
    const float* b_ind = (const float*)d_in[3];
    const float* a_ind = (const float*)d_in[4];
    const float* W_rev = (const float*)d_in[5];
    const float* b_rev = (const float*)d_in[6];
    const float* a_rev = (const float*)d_in[7];
    const float* W_dd  = (const float*)d_in[8];
    const float* b_dd  = (const float*)d_in[9];
    const float* a_dd  = (const float*)d_in[10];
    const int* src_ind = (const int*)d_in[11];
    const int* dst_ind = (const int*)d_in[12];
    const int* src_rev = (const int*)d_in[13];
    const int* dst_rev = (const int*)d_in[14];
    const int* src_dd  = (const int*)d_in[15];
    const int* dst_dd  = (const int*)d_in[16];

    float* out    = (float*)d_out;
    float* h_drug = out;
    float* h_dis  = out + (size_t)N_DRUG * DIM;

    float *el_ind, *er_rev, *el_rev, *er_ind, *el_dd, *er_dd;
    int* degptr;
    cudaGetSymbolAddress((void**)&el_ind, g_el_ind);
    cudaGetSymbolAddress((void**)&er_rev, g_er_rev);
    cudaGetSymbolAddress((void**)&el_rev, g_el_rev);
    cudaGetSymbolAddress((void**)&er_ind, g_er_ind);
    cudaGetSymbolAddress((void**)&el_dd,  g_el_dd);
    cudaGetSymbolAddress((void**)&er_dd,  g_er_dd);
    cudaGetSymbolAddress((void**)&degptr, g_deg);

    // 1. zero degree counters (memset node)
    cudaMemsetAsync(degptr, 0, 3 * N_DIS * sizeof(int), 0);

    // 2. batched fused GEMM + projections (writes fp16 Wh + scalar keys)
    GemmArgs ga;
    ga.X[0] = feat_drug;    ga.W[0] = W_ind; ga.b[0] = b_ind;
    ga.a1[0] = a_ind;       ga.a2[0] = a_rev + DIM;
    ga.s1[0] = el_ind;      ga.s2[0] = er_rev;

    ga.X[1] = feat_disease; ga.W[1] = W_rev; ga.b[1] = b_rev;
    ga.a1[1] = a_rev;       ga.a2[1] = a_ind + DIM;
    ga.s1[1] = el_rev;      ga.s2[1] = er_ind;

    ga.X[2] = feat_disease; ga.W[2] = W_dd;  ga.b[2] = b_dd;
    ga.a1[2] = a_dd;        ga.a2[2] = a_dd + DIM;
    ga.s1[2] = el_dd;       ga.s2[2] = er_dd;

    dim3 ggrid(N_DRUG / 8, 3);
    gemm_proj_kernel<<<ggrid, 128>>>(ga);

    // etype 0 = ind (drug->dis), 1 = rev (dis->drug), 2 = dd (dis->dis)
    EdgeIdx ei;
    ei.src[0] = src_ind; ei.dst[0] = dst_ind;
    ei.src[1] = src_rev; ei.dst[1] = dst_rev;
    ei.src[2] = src_dd;  ei.dst[2] = dst_dd;

    dim3 egrid((NEDGE + 255) / 256, 3);

    // 3. CSR build: histogram -> 3-phase scan -> scatter (with logit)
    hist_kernel<<<egrid, 256>>>(ei);
    dim3 sgrid(SCAN_NB, 3);
    scan1_kernel<<<sgrid, 256>>>();
    scan2_kernel<<<1, 96>>>();
    scan3_kernel<<<sgrid, 256>>>();
    scatter_kernel<<<egrid, 256>>>(ei);

    // 4. per-dst softmax + aggregation, one warp per dst node
    int total_warps = N_DRUG + N_DIS;
    int ablocks = (total_warps * 32 + 255) / 256;
    aggr_kernel<<<ablocks, 256>>>(h_drug, h_dis);
}

// round 5
// speedup vs baseline: 3.4351x; 1.4531x over previous
#include <cuda_runtime.h>
#include <cuda_fp16.h>
#include <mma.h>
#include <math.h>

using namespace nvcuda;

#define N_DRUG 20000
#define N_DIS  20000
#define NEDGE  300000
#define DIM    128

#define SCAN_ELEMS 1024
#define SCAN_NB    ((N_DIS + SCAN_ELEMS - 1) / SCAN_ELEMS)   // 20
#define OFF_STRIDE (N_DIS + 4)

#define GROWS 64                       // GEMM rows per block
#define GBLKS ((N_DRUG + GROWS - 1) / GROWS)   // 313

// ---------------- scratch (device globals; no allocation allowed) ----------
__device__ __half g_Whh[3][N_DIS * DIM];     // fp16 Wh per etype (gather source)
__device__ __half g_W16[3][DIM * DIM];       // fp16 weights

__device__ float g_el_ind[N_DRUG];
__device__ float g_er_rev[N_DRUG];
__device__ float g_el_rev[N_DIS];
__device__ float g_er_ind[N_DIS];
__device__ float g_el_dd [N_DIS];
__device__ float g_er_dd [N_DIS];

__device__ int   g_deg[3][N_DIS];
__device__ int   g_off[3][OFF_STRIDE];
__device__ int   g_cur[3][N_DIS];
__device__ int   g_bsum[3][SCAN_NB];
__device__ int   g_src_s[3][NEDGE];
__device__ float g_e_s  [3][NEDGE];

// ---------------- param structs ---------------------------------------------
struct GemmArgs {
    const float* X[3];
    const float* b[3];
    const float* a1[3];
    const float* a2[3];
    float* s1[3];
    float* s2[3];
};

struct PrepArgs {
    const float* W[3];
};

struct EdgeIdx {
    const int* src[3];
    const int* dst[3];
};

// ---------------- helpers ----------------------------------------------------
__device__ __forceinline__ float leaky(float x) {
    return x > 0.0f ? x : 0.01f * x;
}

__device__ __forceinline__ void red_add_v4(float* addr, float4 v) {
    asm volatile("red.global.add.v4.f32 [%0], {%1,%2,%3,%4};"
                 :: "l"(addr), "f"(v.x), "f"(v.y), "f"(v.z), "f"(v.w)
                 : "memory");
}

// ---------------- prep: zero degree counters + convert W to fp16 -------------
__global__ void prep_kernel(PrepArgs pa) {
    int i = blockIdx.x * blockDim.x + threadIdx.x;
    if (i < 3 * N_DIS) (&g_deg[0][0])[i] = 0;
    if (i < 3 * DIM * DIM) {
        int t = i / (DIM * DIM);
        int k = i - t * DIM * DIM;
        g_W16[t][k] = __float2half(pa.W[t][k]);
    }
}

// ---------------- WMMA GEMM + bias + attention scalar projections ------------
// Block: 128 threads (4 warps), 64 rows x 128 cols per block, K=128 in 2 chunks.
__global__ void __launch_bounds__(128) gemm_wmma_kernel(GemmArgs ga) {
    const int t = blockIdx.y;
    const int row0 = blockIdx.x * GROWS;
    const float* __restrict__ X  = ga.X[t];
    const __half* __restrict__ Wg = g_W16[t];

    __shared__ union {
        struct {
            __half Xs[GROWS][72];     // 64 rows x 64-col k-chunk (pad 8)
            __half Ws[64][136];       // 64 k-rows x 128 n (pad 8)
        } mm;
        float ep[4][16][132];         // per-warp epilogue tile
    } sm;

    int tid  = threadIdx.x;
    int warp = tid >> 5;
    int lane = tid & 31;

    wmma::fragment<wmma::accumulator, 16, 16, 16, float> acc[8];
    #pragma unroll
    for (int n = 0; n < 8; n++) wmma::fill_fragment(acc[n], 0.0f);

    for (int chunk = 0; chunk < 2; chunk++) {
        __syncthreads();
        // load X k-chunk (fp32 -> half)
        {
            int r  = tid >> 4;
            int cg = (tid & 15) * 4;
            #pragma unroll
            for (int rr = r; rr < GROWS; rr += 8) {
                int grow = row0 + rr;
                float4 x4 = make_float4(0.f, 0.f, 0.f, 0.f);
                if (grow < N_DRUG)
                    x4 = *(const float4*)&X[(size_t)grow * DIM + chunk * 64 + cg];
                *(__half2*)&sm.mm.Xs[rr][cg]     = __floats2half2_rn(x4.x, x4.y);
                *(__half2*)&sm.mm.Xs[rr][cg + 2] = __floats2half2_rn(x4.z, x4.w);
            }
        }
        // load W k-chunk (half)
        {
            int r  = tid >> 4;
            int wc = (tid & 15) * 8;
            #pragma unroll
            for (int rr = r; rr < 64; rr += 8) {
                uint4 u = *(const uint4*)&Wg[(chunk * 64 + rr) * DIM + wc];
                *(uint4*)&sm.mm.Ws[rr][wc] = u;
            }
        }
        __syncthreads();

        #pragma unroll
        for (int k2 = 0; k2 < 4; k2++) {
            wmma::fragment<wmma::matrix_a, 16, 16, 16, __half, wmma::row_major> a;
            wmma::load_matrix_sync(a, &sm.mm.Xs[warp * 16][k2 * 16], 72);
            #pragma unroll
            for (int n = 0; n < 8; n++) {
                wmma::fragment<wmma::matrix_b, 16, 16, 16, __half, wmma::row_major> bf;
                wmma::load_matrix_sync(bf, &sm.mm.Ws[k2 * 16][n * 16], 136);
                wmma::mma_sync(acc[n], a, bf, acc[n]);
            }
        }
    }

    __syncthreads();
    #pragma unroll
    for (int n = 0; n < 8; n++)
        wmma::store_matrix_sync(&sm.ep[warp][0][n * 16], acc[n], 132,
                                wmma::mem_row_major);

    // epilogue: bias, fp16 Wh store, el/er projections
    float4 b4  = *(const float4*)&ga.b[t][lane * 4];
    float4 a14 = *(const float4*)&ga.a1[t][lane * 4];
    float4 a24 = *(const float4*)&ga.a2[t][lane * 4];
    __half* __restrict__ Whh = g_Whh[t];

    #pragma unroll 4
    for (int r = 0; r < 16; r++) {
        int grow = row0 + warp * 16 + r;
        if (grow >= N_DRUG) break;
        float4 v = *(const float4*)&sm.ep[warp][r][lane * 4];
        v.x += b4.x; v.y += b4.y; v.z += b4.z; v.w += b4.w;

        __half2 h0 = __floats2half2_rn(v.x, v.y);
        __half2 h1 = __floats2half2_rn(v.z, v.w);
        uint2 u;
        u.x = *(unsigned*)&h0;
        u.y = *(unsigned*)&h1;
        *(uint2*)&Whh[(size_t)grow * DIM + lane * 4] = u;

        float p1 = v.x * a14.x + v.y * a14.y + v.z * a14.z + v.w * a14.w;
        float p2 = v.x * a24.x + v.y * a24.y + v.z * a24.z + v.w * a24.w;
        #pragma unroll
        for (int o = 16; o > 0; o >>= 1) {
            p1 += __shfl_down_sync(0xFFFFFFFFu, p1, o);
            p2 += __shfl_down_sync(0xFFFFFFFFu, p2, o);
        }
        if (lane == 0) { ga.s1[t][grow] = p1; ga.s2[t][grow] = p2; }
    }
}

// ---------------- histogram ---------------------------------------------------
__global__ void hist_kernel(EdgeIdx ei) {
    int t = blockIdx.y;
    int i = blockIdx.x * blockDim.x + threadIdx.x;
    if (i >= NEDGE) return;
    atomicAdd(&g_deg[t][ei.dst[t][i]], 1);
}

// ---------------- scan phase 1: per-block partial sums -----------------------
__global__ void __launch_bounds__(256) scan1_kernel() {
    int t   = blockIdx.y;
    int b   = blockIdx.x;
    int tid = threadIdx.x;
    int idx = b * SCAN_ELEMS + tid * 4;

    int4 v = (idx < N_DIS) ? *(const int4*)&g_deg[t][idx]
                           : make_int4(0, 0, 0, 0);
    int s = v.x + v.y + v.z + v.w;

    int lane = tid & 31, wid = tid >> 5;
    #pragma unroll
    for (int o = 16; o > 0; o >>= 1)
        s += __shfl_down_sync(0xFFFFFFFFu, s, o);

    __shared__ int ws[8];
    if (lane == 0) ws[wid] = s;
    __syncthreads();
    if (tid == 0) {
        int tot = 0;
        #pragma unroll
        for (int i = 0; i < 8; i++) tot += ws[i];
        g_bsum[t][b] = tot;
        if (b == 0) g_off[t][N_DIS] = NEDGE;
    }
}

// ---------------- scan phase 2 (merged): final offsets ------------------------
__global__ void __launch_bounds__(256) scan3_kernel() {
    int t   = blockIdx.y;
    int b   = blockIdx.x;
    int tid = threadIdx.x;
    int idx = b * SCAN_ELEMS + tid * 4;
    int lane = tid & 31, wid = tid >> 5;

    // block base = sum of g_bsum[t][0..b-1], computed redundantly by warp 0
    __shared__ int s_base;
    if (wid == 0) {
        int v = (lane < b && lane < SCAN_NB) ? g_bsum[t][lane] : 0;
        #pragma unroll
        for (int o = 16; o > 0; o >>= 1)
            v += __shfl_down_sync(0xFFFFFFFFu, v, o);
        if (lane == 0) s_base = v;
    }

    int4 v = (idx < N_DIS) ? *(const int4*)&g_deg[t][idx]
                           : make_int4(0, 0, 0, 0);
    int s = v.x + v.y + v.z + v.w;

    int x = s;
    #pragma unroll
    for (int o = 1; o < 32; o <<= 1) {
        int y = __shfl_up_sync(0xFFFFFFFFu, x, o);
        if (lane >= o) x += y;
    }
    __shared__ int ws[8];
    if (lane == 31) ws[wid] = x;
    __syncthreads();
    if (wid == 0 && lane < 8) {
        int w = ws[lane];
        #pragma unroll
        for (int o = 1; o < 8; o <<= 1) {
            int y = __shfl_up_sync(0xFFu, w, o);
            if (lane >= o) w += y;
        }
        ws[lane] = w;
    }
    __syncthreads();

    int blockExcl = ((wid > 0) ? ws[wid - 1] : 0) + (x - s);
    int base = s_base + blockExcl;

    if (idx < N_DIS) {
        int4 o;
        o.x = base;
        o.y = o.x + v.x;
        o.z = o.y + v.y;
        o.w = o.z + v.z;
        *(int4*)&g_off[t][idx] = o;
        *(int4*)&g_cur[t][idx] = o;
    }
}

// ---------------- scatter: build dst-sorted (src, logit) lists ---------------
__global__ void scatter_kernel(EdgeIdx ei) {
    int t = blockIdx.y;
    int i = blockIdx.x * blockDim.x + threadIdx.x;
    if (i >= NEDGE) return;
    const float* el_tab[3] = {g_el_ind, g_el_rev, g_el_dd};
    const float* er_tab[3] = {g_er_ind, g_er_rev, g_er_dd};
    int si = ei.src[t][i];
    int di = ei.dst[t][i];
    float e = leaky(el_tab[t][si] + er_tab[t][di]);
    int pos = atomicAdd(&g_cur[t][di], 1);
    g_src_s[t][pos] = si;
    g_e_s[t][pos]   = e;
}

// ---------------- per-(dst,etype) softmax + aggregation (warp per task) ------
__global__ void __launch_bounds__(256) aggr_kernel(float* __restrict__ h_drug,
                                                   float* __restrict__ h_dis)
{
    int gw   = (blockIdx.x * blockDim.x + threadIdx.x) >> 5;
    int lane = threadIdx.x & 31;

    int t, d;
    float* outrow;
    if (gw < N_DRUG)               { t = 1; d = gw;                    outrow = h_drug + (size_t)d * DIM; }
    else if (gw < N_DRUG + N_DIS)  { t = 0; d = gw - N_DRUG;           outrow = h_dis  + (size_t)d * DIM; }
    else if (gw < N_DRUG + 2*N_DIS){ t = 2; d = gw - N_DRUG - N_DIS;   outrow = h_dis  + (size_t)d * DIM; }
    else return;

    int lo = g_off[t][d];
    int hi = g_off[t][d + 1];
    if (hi <= lo) return;

    const __half* __restrict__ Wh = g_Whh[t];

    float mx = -INFINITY;
    for (int k = lo + lane; k < hi; k += 32)
        mx = fmaxf(mx, g_e_s[t][k]);
    #pragma unroll
    for (int o = 16; o > 0; o >>= 1)
        mx = fmaxf(mx, __shfl_xor_sync(0xFFFFFFFFu, mx, o));

    float sm = 0.f;
    for (int k = lo + lane; k < hi; k += 32)
        sm += __expf(g_e_s[t][k] - mx);
    #pragma unroll
    for (int o = 16; o > 0; o >>= 1)
        sm += __shfl_xor_sync(0xFFFFFFFFu, sm, o);
    float inv = 1.0f / sm;

    float4 acc = make_float4(0.f, 0.f, 0.f, 0.f);
    for (int base = lo; base < hi; base += 32) {
        int n = min(32, hi - base);
        int   s = 0;
        float p = 0.f;
        if (lane < n) {
            s = g_src_s[t][base + lane];
            p = __expf(g_e_s[t][base + lane] - mx) * inv;
        }
        #pragma unroll 8
        for (int j = 0; j < n; j++) {
            int   sj = __shfl_sync(0xFFFFFFFFu, s, j);
            float pj = __shfl_sync(0xFFFFFFFFu, p, j);
            uint2 u = ((const uint2*)(Wh + (size_t)sj * DIM))[lane];
            __half2 h0 = *(__half2*)&u.x;
            __half2 h1 = *(__half2*)&u.y;
            float2 f0 = __half22float2(h0);
            float2 f1 = __half22float2(h1);
            acc.x += pj * f0.x;
            acc.y += pj * f0.y;
            acc.z += pj * f1.x;
            acc.w += pj * f1.y;
        }
    }
    red_add_v4(outrow + lane * 4, acc);
}

// ---------------- launch -----------------------------------------------------
extern "C" void kernel_launch(void* const* d_in, const int* in_sizes, int n_in,
                              void* d_out, int out_size)
{
    const float* feat_drug    = (const float*)d_in[0];
    const float* feat_disease = (const float*)d_in[1];
    const float* W_ind = (const float*)d_in[2];
    const float* b_ind = (const float*)d_in[3];
    const float* a_ind = (const float*)d_in[4];
    const float* W_rev = (const float*)d_in[5];
    const float* b_rev = (const float*)d_in[6];
    const float* a_rev = (const float*)d_in[7];
    const float* W_dd  = (const float*)d_in[8];
    const float* b_dd  = (const float*)d_in[9];
    const float* a_dd  = (const float*)d_in[10];
    const int* src_ind = (const int*)d_in[11];
    const int* dst_ind = (const int*)d_in[12];
    const int* src_rev = (const int*)d_in[13];
    const int* dst_rev = (const int*)d_in[14];
    const int* src_dd  = (const int*)d_in[15];
    const int* dst_dd  = (const int*)d_in[16];

    float* out    = (float*)d_out;
    float* h_drug = out;
    float* h_dis  = out + (size_t)N_DRUG * DIM;

    float *el_ind, *er_rev, *el_rev, *er_ind, *el_dd, *er_dd;
    cudaGetSymbolAddress((void**)&el_ind, g_el_ind);
    cudaGetSymbolAddress((void**)&er_rev, g_er_rev);
    cudaGetSymbolAddress((void**)&el_rev, g_el_rev);
    cudaGetSymbolAddress((void**)&er_ind, g_er_ind);
    cudaGetSymbolAddress((void**)&el_dd,  g_el_dd);
    cudaGetSymbolAddress((void**)&er_dd,  g_er_dd);

    // 1. zero output (aggregation uses red.add), prep (deg=0, W->fp16)
    cudaMemsetAsync(d_out, 0, (size_t)out_size * sizeof(float), 0);
    PrepArgs pa;
    pa.W[0] = W_ind; pa.W[1] = W_rev; pa.W[2] = W_dd;
    prep_kernel<<<(3 * N_DIS + 255) / 256, 256>>>(pa);

    // 2. tensor-core GEMM + projections
    GemmArgs ga;
    ga.X[0] = feat_drug;    ga.b[0] = b_ind;
    ga.a1[0] = a_ind;       ga.a2[0] = a_rev + DIM;
    ga.s1[0] = el_ind;      ga.s2[0] = er_rev;

    ga.X[1] = feat_disease; ga.b[1] = b_rev;
    ga.a1[1] = a_rev;       ga.a2[1] = a_ind + DIM;
    ga.s1[1] = el_rev;      ga.s2[1] = er_ind;

    ga.X[2] = feat_disease; ga.b[2] = b_dd;
    ga.a1[2] = a_dd;        ga.a2[2] = a_dd + DIM;
    ga.s1[2] = el_dd;       ga.s2[2] = er_dd;

    dim3 ggrid(GBLKS, 3);
    gemm_wmma_kernel<<<ggrid, 128>>>(ga);

    // etype 0 = ind (drug->dis), 1 = rev (dis->drug), 2 = dd (dis->dis)
    EdgeIdx ei;
    ei.src[0] = src_ind; ei.dst[0] = dst_ind;
    ei.src[1] = src_rev; ei.dst[1] = dst_rev;
    ei.src[2] = src_dd;  ei.dst[2] = dst_dd;

    dim3 egrid((NEDGE + 255) / 256, 3);

    // 3. CSR build: histogram -> 2-phase scan -> scatter (with logit)
    hist_kernel<<<egrid, 256>>>(ei);
    dim3 sgrid(SCAN_NB, 3);
    scan1_kernel<<<sgrid, 256>>>();
    scan3_kernel<<<sgrid, 256>>>();
    scatter_kernel<<<egrid, 256>>>(ei);

    // 4. per-(dst,etype) softmax + aggregation, one warp per task
    int total_warps = N_DRUG + 2 * N_DIS;
    int ablocks = (total_warps * 32 + 255) / 256;
    aggr_kernel<<<ablocks, 256>>>(h_drug, h_dis);
}

// round 6
// speedup vs baseline: 4.2786x; 1.2456x over previous
#include <cuda_runtime.h>
#include <cuda_fp16.h>
#include <mma.h>
#include <math.h>

using namespace nvcuda;

#define N_DRUG 20000
#define N_DIS  20000
#define NEDGE  300000
#define DIM    128

#define SCAN_ELEMS 1024
#define SCAN_NB    ((N_DIS + SCAN_ELEMS - 1) / SCAN_ELEMS)   // 20
#define OFF_STRIDE (N_DIS + 4)

#define GROWS 64
#define GBLKS ((N_DRUG + GROWS - 1) / GROWS)   // 313

// ---------------- scratch (device globals; no allocation allowed) ----------
__device__ __half g_Whh[3][N_DIS * DIM];     // fp16 Wh per etype (gather source)

__device__ float g_el_ind[N_DRUG];
__device__ float g_er_rev[N_DRUG];
__device__ float g_el_rev[N_DIS];
__device__ float g_er_ind[N_DIS];
__device__ float g_el_dd [N_DIS];
__device__ float g_er_dd [N_DIS];

__device__ int   g_deg[3][N_DIS];
__device__ int   g_off[3][OFF_STRIDE];
__device__ int   g_cur[3][N_DIS];
__device__ int   g_bsum[3][SCAN_NB];
__device__ int2  g_edge[3][NEDGE];           // packed (src, logit-bits), dst-sorted

// ---------------- param structs ---------------------------------------------
struct GemmArgs {
    const float* X[3];
    const float* W[3];
    const float* b[3];
    const float* a1[3];
    const float* a2[3];
    float* s1[3];
    float* s2[3];
};

struct EdgeIdx {
    const int* src[3];
    const int* dst[3];
};

// ---------------- helpers ----------------------------------------------------
__device__ __forceinline__ float leaky(float x) {
    return x > 0.0f ? x : 0.01f * x;
}

__device__ __forceinline__ void red_add_v4(float* addr, float4 v) {
    asm volatile("red.global.add.v4.f32 [%0], {%1,%2,%3,%4};"
                 :: "l"(addr), "f"(v.x), "f"(v.y), "f"(v.z), "f"(v.w)
                 : "memory");
}

// ---------------- WMMA GEMM + bias + attention scalar projections ------------
// Block: 128 threads (4 warps), 64 rows x 128 cols, K=128 in 2 chunks.
// W is converted fp32 -> fp16 inline while staging to smem.
__global__ void __launch_bounds__(128) gemm_wmma_kernel(GemmArgs ga) {
    const int t = blockIdx.y;
    const int row0 = blockIdx.x * GROWS;
    const float* __restrict__ X  = ga.X[t];
    const float* __restrict__ Wg = ga.W[t];

    __shared__ union {
        struct {
            __half Xs[GROWS][72];
            __half Ws[64][136];
        } mm;
        float ep[4][16][132];
    } sm;

    int tid  = threadIdx.x;
    int warp = tid >> 5;
    int lane = tid & 31;

    wmma::fragment<wmma::accumulator, 16, 16, 16, float> acc[8];
    #pragma unroll
    for (int n = 0; n < 8; n++) wmma::fill_fragment(acc[n], 0.0f);

    for (int chunk = 0; chunk < 2; chunk++) {
        __syncthreads();
        // stage X k-chunk (fp32 -> half)
        {
            int r  = tid >> 4;
            int cg = (tid & 15) * 4;
            #pragma unroll
            for (int rr = r; rr < GROWS; rr += 8) {
                int grow = row0 + rr;
                float4 x4 = make_float4(0.f, 0.f, 0.f, 0.f);
                if (grow < N_DRUG)
                    x4 = *(const float4*)&X[(size_t)grow * DIM + chunk * 64 + cg];
                *(__half2*)&sm.mm.Xs[rr][cg]     = __floats2half2_rn(x4.x, x4.y);
                *(__half2*)&sm.mm.Xs[rr][cg + 2] = __floats2half2_rn(x4.z, x4.w);
            }
        }
        // stage W k-chunk (fp32 -> half inline)
        {
            int r  = tid >> 4;
            int wc = (tid & 15) * 8;
            #pragma unroll
            for (int rr = r; rr < 64; rr += 8) {
                const float* wp = &Wg[(size_t)(chunk * 64 + rr) * DIM + wc];
                float4 f0 = *(const float4*)wp;
                float4 f1 = *(const float4*)(wp + 4);
                __half2 h0 = __floats2half2_rn(f0.x, f0.y);
                __half2 h1 = __floats2half2_rn(f0.z, f0.w);
                __half2 h2 = __floats2half2_rn(f1.x, f1.y);
                __half2 h3 = __floats2half2_rn(f1.z, f1.w);
                uint4 u;
                u.x = *(unsigned*)&h0; u.y = *(unsigned*)&h1;
                u.z = *(unsigned*)&h2; u.w = *(unsigned*)&h3;
                *(uint4*)&sm.mm.Ws[rr][wc] = u;
            }
        }
        __syncthreads();

        #pragma unroll
        for (int k2 = 0; k2 < 4; k2++) {
            wmma::fragment<wmma::matrix_a, 16, 16, 16, __half, wmma::row_major> a;
            wmma::load_matrix_sync(a, &sm.mm.Xs[warp * 16][k2 * 16], 72);
            #pragma unroll
            for (int n = 0; n < 8; n++) {
                wmma::fragment<wmma::matrix_b, 16, 16, 16, __half, wmma::row_major> bf;
                wmma::load_matrix_sync(bf, &sm.mm.Ws[k2 * 16][n * 16], 136);
                wmma::mma_sync(acc[n], a, bf, acc[n]);
            }
        }
    }

    __syncthreads();
    #pragma unroll
    for (int n = 0; n < 8; n++)
        wmma::store_matrix_sync(&sm.ep[warp][0][n * 16], acc[n], 132,
                                wmma::mem_row_major);

    float4 b4  = *(const float4*)&ga.b[t][lane * 4];
    float4 a14 = *(const float4*)&ga.a1[t][lane * 4];
    float4 a24 = *(const float4*)&ga.a2[t][lane * 4];
    __half* __restrict__ Whh = g_Whh[t];

    #pragma unroll 4
    for (int r = 0; r < 16; r++) {
        int grow = row0 + warp * 16 + r;
        if (grow >= N_DRUG) break;
        float4 v = *(const float4*)&sm.ep[warp][r][lane * 4];
        v.x += b4.x; v.y += b4.y; v.z += b4.z; v.w += b4.w;

        __half2 h0 = __floats2half2_rn(v.x, v.y);
        __half2 h1 = __floats2half2_rn(v.z, v.w);
        uint2 u;
        u.x = *(unsigned*)&h0;
        u.y = *(unsigned*)&h1;
        *(uint2*)&Whh[(size_t)grow * DIM + lane * 4] = u;

        float p1 = v.x * a14.x + v.y * a14.y + v.z * a14.z + v.w * a14.w;
        float p2 = v.x * a24.x + v.y * a24.y + v.z * a24.z + v.w * a24.w;
        #pragma unroll
        for (int o = 16; o > 0; o >>= 1) {
            p1 += __shfl_down_sync(0xFFFFFFFFu, p1, o);
            p2 += __shfl_down_sync(0xFFFFFFFFu, p2, o);
        }
        if (lane == 0) { ga.s1[t][grow] = p1; ga.s2[t][grow] = p2; }
    }
}

// ---------------- histogram ---------------------------------------------------
__global__ void hist_kernel(EdgeIdx ei) {
    int t = blockIdx.y;
    int i = blockIdx.x * blockDim.x + threadIdx.x;
    if (i >= NEDGE) return;
    atomicAdd(&g_deg[t][ei.dst[t][i]], 1);
}

// ---------------- scan phase 1: per-block partial sums -----------------------
__global__ void __launch_bounds__(256) scan1_kernel() {
    int t   = blockIdx.y;
    int b   = blockIdx.x;
    int tid = threadIdx.x;
    int idx = b * SCAN_ELEMS + tid * 4;

    int4 v = (idx < N_DIS) ? *(const int4*)&g_deg[t][idx]
                           : make_int4(0, 0, 0, 0);
    int s = v.x + v.y + v.z + v.w;

    int lane = tid & 31, wid = tid >> 5;
    #pragma unroll
    for (int o = 16; o > 0; o >>= 1)
        s += __shfl_down_sync(0xFFFFFFFFu, s, o);

    __shared__ int ws[8];
    if (lane == 0) ws[wid] = s;
    __syncthreads();
    if (tid == 0) {
        int tot = 0;
        #pragma unroll
        for (int i = 0; i < 8; i++) tot += ws[i];
        g_bsum[t][b] = tot;
        if (b == 0) g_off[t][N_DIS] = NEDGE;
    }
}

// ---------------- scan phase 2: final offsets ---------------------------------
__global__ void __launch_bounds__(256) scan3_kernel() {
    int t   = blockIdx.y;
    int b   = blockIdx.x;
    int tid = threadIdx.x;
    int idx = b * SCAN_ELEMS + tid * 4;
    int lane = tid & 31, wid = tid >> 5;

    __shared__ int s_base;
    if (wid == 0) {
        int v = (lane < b && lane < SCAN_NB) ? g_bsum[t][lane] : 0;
        #pragma unroll
        for (int o = 16; o > 0; o >>= 1)
            v += __shfl_down_sync(0xFFFFFFFFu, v, o);
        if (lane == 0) s_base = v;
    }

    int4 v = (idx < N_DIS) ? *(const int4*)&g_deg[t][idx]
                           : make_int4(0, 0, 0, 0);
    int s = v.x + v.y + v.z + v.w;

    int x = s;
    #pragma unroll
    for (int o = 1; o < 32; o <<= 1) {
        int y = __shfl_up_sync(0xFFFFFFFFu, x, o);
        if (lane >= o) x += y;
    }
    __shared__ int ws[8];
    if (lane == 31) ws[wid] = x;
    __syncthreads();
    if (wid == 0 && lane < 8) {
        int w = ws[lane];
        #pragma unroll
        for (int o = 1; o < 8; o <<= 1) {
            int y = __shfl_up_sync(0xFFu, w, o);
            if (lane >= o) w += y;
        }
        ws[lane] = w;
    }
    __syncthreads();

    int blockExcl = ((wid > 0) ? ws[wid - 1] : 0) + (x - s);
    int base = s_base + blockExcl;

    if (idx < N_DIS) {
        int4 o;
        o.x = base;
        o.y = o.x + v.x;
        o.z = o.y + v.y;
        o.w = o.z + v.z;
        *(int4*)&g_off[t][idx] = o;
        *(int4*)&g_cur[t][idx] = o;
    }
}

// ---------------- scatter: build dst-sorted packed (src, logit) --------------
__global__ void scatter_kernel(EdgeIdx ei) {
    int t = blockIdx.y;
    int i = blockIdx.x * blockDim.x + threadIdx.x;
    if (i >= NEDGE) return;
    const float* el_tab[3] = {g_el_ind, g_el_rev, g_el_dd};
    const float* er_tab[3] = {g_er_ind, g_er_rev, g_er_dd};
    int si = ei.src[t][i];
    int di = ei.dst[t][i];
    float e = leaky(el_tab[t][si] + er_tab[t][di]);
    int pos = atomicAdd(&g_cur[t][di], 1);
    int2 pk;
    pk.x = si;
    pk.y = __float_as_int(e);
    g_edge[t][pos] = pk;
}

// ---------------- per-(dst,etype) softmax + aggregation (warp per task) ------
__global__ void __launch_bounds__(256) aggr_kernel(float* __restrict__ h_drug,
                                                   float* __restrict__ h_dis)
{
    int gw   = (blockIdx.x * blockDim.x + threadIdx.x) >> 5;
    int lane = threadIdx.x & 31;

    int t, d;
    float* outrow;
    if (gw < N_DRUG)               { t = 1; d = gw;                    outrow = h_drug + (size_t)d * DIM; }
    else if (gw < N_DRUG + N_DIS)  { t = 0; d = gw - N_DRUG;           outrow = h_dis  + (size_t)d * DIM; }
    else if (gw < N_DRUG + 2*N_DIS){ t = 2; d = gw - N_DRUG - N_DIS;   outrow = h_dis  + (size_t)d * DIM; }
    else return;

    int lo = g_off[t][d];
    int hi = g_off[t][d + 1];
    int len = hi - lo;
    if (len <= 0) return;

    const __half* __restrict__ Wh = g_Whh[t];
    float4 acc = make_float4(0.f, 0.f, 0.f, 0.f);

    if (len <= 32) {
        // single-chunk fast path: edge list read exactly once
        int2 pk = (lane < len) ? g_edge[t][lo + lane]
                               : make_int2(0, 0xFF800000);   // -inf
        float e = __int_as_float(pk.y);

        float mx = e;
        #pragma unroll
        for (int o = 16; o > 0; o >>= 1)
            mx = fmaxf(mx, __shfl_xor_sync(0xFFFFFFFFu, mx, o));

        float p = __expf(e - mx);                // 0 for inactive lanes
        float sm = p;
        #pragma unroll
        for (int o = 16; o > 0; o >>= 1)
            sm += __shfl_xor_sync(0xFFFFFFFFu, sm, o);
        p *= (1.0f / sm);

        #pragma unroll 8
        for (int j = 0; j < len; j++) {
            int   sj = __shfl_sync(0xFFFFFFFFu, pk.x, j);
            float pj = __shfl_sync(0xFFFFFFFFu, p, j);
            uint2 u = ((const uint2*)(Wh + (size_t)sj * DIM))[lane];
            float2 f0 = __half22float2(*(__half2*)&u.x);
            float2 f1 = __half22float2(*(__half2*)&u.y);
            acc.x += pj * f0.x;
            acc.y += pj * f0.y;
            acc.z += pj * f1.x;
            acc.w += pj * f1.y;
        }
    } else {
        float mx = -INFINITY;
        for (int k = lo + lane; k < hi; k += 32)
            mx = fmaxf(mx, __int_as_float(g_edge[t][k].y));
        #pragma unroll
        for (int o = 16; o > 0; o >>= 1)
            mx = fmaxf(mx, __shfl_xor_sync(0xFFFFFFFFu, mx, o));

        float sm = 0.f;
        for (int k = lo + lane; k < hi; k += 32)
            sm += __expf(__int_as_float(g_edge[t][k].y) - mx);
        #pragma unroll
        for (int o = 16; o > 0; o >>= 1)
            sm += __shfl_xor_sync(0xFFFFFFFFu, sm, o);
        float inv = 1.0f / sm;

        for (int base = lo; base < hi; base += 32) {
            int n = min(32, hi - base);
            int   s = 0;
            float p = 0.f;
            if (lane < n) {
                int2 pk = g_edge[t][base + lane];
                s = pk.x;
                p = __expf(__int_as_float(pk.y) - mx) * inv;
            }
            #pragma unroll 8
            for (int j = 0; j < n; j++) {
                int   sj = __shfl_sync(0xFFFFFFFFu, s, j);
                float pj = __shfl_sync(0xFFFFFFFFu, p, j);
                uint2 u = ((const uint2*)(Wh + (size_t)sj * DIM))[lane];
                float2 f0 = __half22float2(*(__half2*)&u.x);
                float2 f1 = __half22float2(*(__half2*)&u.y);
                acc.x += pj * f0.x;
                acc.y += pj * f0.y;
                acc.z += pj * f1.x;
                acc.w += pj * f1.y;
            }
        }
    }
    red_add_v4(outrow + lane * 4, acc);
}

// ---------------- launch -----------------------------------------------------
extern "C" void kernel_launch(void* const* d_in, const int* in_sizes, int n_in,
                              void* d_out, int out_size)
{
    const float* feat_drug    = (const float*)d_in[0];
    const float* feat_disease = (const float*)d_in[1];
    const float* W_ind = (const float*)d_in[2];
    const float* b_ind = (const float*)d_in[3];
    const float* a_ind = (const float*)d_in[4];
    const float* W_rev = (const float*)d_in[5];
    const float* b_rev = (const float*)d_in[6];
    const float* a_rev = (const float*)d_in[7];
    const float* W_dd  = (const float*)d_in[8];
    const float* b_dd  = (const float*)d_in[9];
    const float* a_dd  = (const float*)d_in[10];
    const int* src_ind = (const int*)d_in[11];
    const int* dst_ind = (const int*)d_in[12];
    const int* src_rev = (const int*)d_in[13];
    const int* dst_rev = (const int*)d_in[14];
    const int* src_dd  = (const int*)d_in[15];
    const int* dst_dd  = (const int*)d_in[16];

    float* out    = (float*)d_out;
    float* h_drug = out;
    float* h_dis  = out + (size_t)N_DRUG * DIM;

    float *el_ind, *er_rev, *el_rev, *er_ind, *el_dd, *er_dd;
    int* degptr;
    cudaGetSymbolAddress((void**)&el_ind, g_el_ind);
    cudaGetSymbolAddress((void**)&er_rev, g_er_rev);
    cudaGetSymbolAddress((void**)&el_rev, g_el_rev);
    cudaGetSymbolAddress((void**)&er_ind, g_er_ind);
    cudaGetSymbolAddress((void**)&el_dd,  g_el_dd);
    cudaGetSymbolAddress((void**)&er_dd,  g_er_dd);
    cudaGetSymbolAddress((void**)&degptr, g_deg);

    // fork a side stream for the CSR build (independent of the GEMM)
    cudaStream_t s2;
    cudaStreamCreateWithFlags(&s2, cudaStreamNonBlocking);
    cudaEvent_t ev0, ev2;
    cudaEventCreateWithFlags(&ev0, cudaEventDisableTiming);
    cudaEventCreateWithFlags(&ev2, cudaEventDisableTiming);

    EdgeIdx ei;
    ei.src[0] = src_ind; ei.dst[0] = dst_ind;
    ei.src[1] = src_rev; ei.dst[1] = dst_rev;
    ei.src[2] = src_dd;  ei.dst[2] = dst_dd;

    cudaEventRecord(ev0, 0);
    cudaStreamWaitEvent(s2, ev0, 0);

    // --- side stream: output zero, deg zero, hist, 2-phase scan -------------
    cudaMemsetAsync(d_out, 0, (size_t)out_size * sizeof(float), s2);
    cudaMemsetAsync(degptr, 0, 3 * N_DIS * sizeof(int), s2);
    dim3 egrid((NEDGE + 255) / 256, 3);
    hist_kernel<<<egrid, 256, 0, s2>>>(ei);
    dim3 sgrid(SCAN_NB, 3);
    scan1_kernel<<<sgrid, 256, 0, s2>>>();
    scan3_kernel<<<sgrid, 256, 0, s2>>>();
    cudaEventRecord(ev2, s2);

    // --- main stream: tensor-core GEMM + projections -------------------------
    GemmArgs ga;
    ga.X[0] = feat_drug;    ga.W[0] = W_ind; ga.b[0] = b_ind;
    ga.a1[0] = a_ind;       ga.a2[0] = a_rev + DIM;
    ga.s1[0] = el_ind;      ga.s2[0] = er_rev;

    ga.X[1] = feat_disease; ga.W[1] = W_rev; ga.b[1] = b_rev;
    ga.a1[1] = a_rev;       ga.a2[1] = a_ind + DIM;
    ga.s1[1] = el_rev;      ga.s2[1] = er_ind;

    ga.X[2] = feat_disease; ga.W[2] = W_dd;  ga.b[2] = b_dd;
    ga.a1[2] = a_dd;        ga.a2[2] = a_dd + DIM;
    ga.s1[2] = el_dd;       ga.s2[2] = er_dd;

    dim3 ggrid(GBLKS, 3);
    gemm_wmma_kernel<<<ggrid, 128>>>(ga);

    // --- join, then scatter + aggregation ------------------------------------
    cudaStreamWaitEvent(0, ev2, 0);
    scatter_kernel<<<egrid, 256>>>(ei);

    int total_warps = N_DRUG + 2 * N_DIS;
    int ablocks = (total_warps * 32 + 255) / 256;
    aggr_kernel<<<ablocks, 256>>>(h_drug, h_dis);
}